// round 8
// baseline (speedup 1.0000x reference)
#include <cuda_runtime.h>
#include <math.h>

#define Nn 4096
#define Dd 256
#define Rr 32
#define Kk 3
#define MAXNZ 96
#define SN 32                   /* staged neighbors in attn (fallback beyond) */
#define ETA 0.5f
#define COEFF 0.03125f          /* r/(n*eps^2) = 32/(4096*0.25) */
#define LN_EPS 1e-5f

// ---------------- device scratch ----------------
__device__ float g_H1[Nn*Dd];
__device__ float g_H2[Nn*Dd];
__device__ float g_ZT[Kk*Nn*Rr];       // [k][n][r]
__device__ float g_part[Kk*32*Rr*Rr];  // [k][chunk][32*32]
__device__ float g_Minv[Kk*Rr*Rr];
__device__ float g_Gcat[Nn*Kk*Rr];     // [n][k*32+r], pre-scaled by ETA*w_k
__device__ int   g_nnz[Nn];            // true count
__device__ int   g_nnzp[Nn];           // padded to multiple of 8 (pad: col=row, val=0)
__device__ int   g_cols[Nn*MAXNZ];
__device__ float g_vals[Nn*MAXNZ];
__device__ float g_w[Kk];
__device__ float g_lap[Kk];

__device__ __forceinline__ float warp_sum(float v) {
    #pragma unroll
    for (int o = 16; o; o >>= 1) v += __shfl_xor_sync(0xFFFFFFFFu, v, o);
    return v;
}
__device__ __forceinline__ float warp_max(float v) {
    #pragma unroll
    for (int o = 16; o; o >>= 1) v = fmaxf(v, __shfl_xor_sync(0xFFFFFFFFu, v, o));
    return v;
}

// ---------------- setup ----------------
__global__ void k_setup(const float* lam, const float* hw, float* tail) {
    if (threadIdx.x == 0) {
        float h0 = hw[0], h1 = hw[1], h2 = hw[2];
        float mx = fmaxf(h0, fmaxf(h1, h2));
        float e0 = expf(h0 - mx), e1 = expf(h1 - mx), e2 = expf(h2 - mx);
        float inv = 1.0f / (e0 + e1 + e2);
        g_w[0] = e0 * inv; g_w[1] = e1 * inv; g_w[2] = e2 * inv;
        for (int k = 0; k < Kk; k++) g_lap[k] = log1pf(expf(lam[k]));
        tail[0] = 0.0f; tail[1] = 0.0f;
        tail[2] = g_w[0]; tail[3] = g_w[1]; tail[4] = g_w[2];
    }
}

// ---------------- CSR extraction (blocks 0..511) + orth loss (blocks 512..517) ----------------
__global__ void k_csr_orth(const float* __restrict__ A, const float* __restrict__ U,
                           float* __restrict__ orth_dst) {
    if (blockIdx.x < 512) {
        int warp = threadIdx.x >> 5, lane = threadIdx.x & 31;
        int row = blockIdx.x * 8 + warp;
        const float4* ar = (const float4*)(A + (size_t)row * Nn);
        unsigned mlt = (1u << lane) - 1u;
        int base = 0;
        for (int c0 = 0; c0 < Nn / 4; c0 += 32) {
            float4 v = ar[c0 + lane];
            unsigned b0 = __ballot_sync(0xFFFFFFFFu, v.x != 0.0f);
            unsigned b1 = __ballot_sync(0xFFFFFFFFu, v.y != 0.0f);
            unsigned b2 = __ballot_sync(0xFFFFFFFFu, v.z != 0.0f);
            unsigned b3 = __ballot_sync(0xFFFFFFFFu, v.w != 0.0f);
            int pos = base + __popc(b0 & mlt) + __popc(b1 & mlt)
                           + __popc(b2 & mlt) + __popc(b3 & mlt);
            int cbase = (c0 + lane) * 4;
            if (v.x != 0.0f && pos < MAXNZ) { g_cols[row*MAXNZ+pos] = cbase;     g_vals[row*MAXNZ+pos] = v.x; pos++; }
            if (v.y != 0.0f && pos < MAXNZ) { g_cols[row*MAXNZ+pos] = cbase + 1; g_vals[row*MAXNZ+pos] = v.y; pos++; }
            if (v.z != 0.0f && pos < MAXNZ) { g_cols[row*MAXNZ+pos] = cbase + 2; g_vals[row*MAXNZ+pos] = v.z; pos++; }
            if (v.w != 0.0f && pos < MAXNZ) { g_cols[row*MAXNZ+pos] = cbase + 3; g_vals[row*MAXNZ+pos] = v.w; pos++; }
            base += __popc(b0) + __popc(b1) + __popc(b2) + __popc(b3);
        }
        if (base > MAXNZ) base = MAXNZ;
        int padded = (base + 7) & ~7;
        if (padded > MAXNZ) padded = MAXNZ;
        for (int i = base + lane; i < padded; i += 32) {
            g_cols[row * MAXNZ + i] = row;
            g_vals[row * MAXNZ + i] = 0.0f;
        }
        if (lane == 0) { g_nnz[row] = base; g_nnzp[row] = padded; }
    } else {
        const int pk[6] = {0,0,0,1,1,2}, pl[6] = {0,1,2,1,2,2};
        int p = blockIdx.x - 512;
        int k = pk[p], l = pl[p];
        int ab = threadIdx.x >> 5, b = threadIdx.x & 31;
        const float* Ua = U + k * Dd * Rr;
        const float* Ub = U + l * Dd * Rr;
        float tot = 0.0f;
        for (int ao = 0; ao < 4; ao++) {
            int a = ao * 8 + ab;
            float g = 0.0f;
            #pragma unroll 8
            for (int d = 0; d < Dd; d++) g += Ua[d * Rr + a] * Ub[d * Rr + b];
            if (k == l && a == b) g -= 1.0f;
            tot += g * g;
        }
        __shared__ float wred[8];
        int w = threadIdx.x >> 5, lane = threadIdx.x & 31;
        float s = warp_sum(tot);
        if (lane == 0) wred[w] = s;
        __syncthreads();
        if (threadIdx.x == 0) {
            float t = 0.0f;
            #pragma unroll
            for (int q = 0; q < 8; q++) t += wred[q];
            atomicAdd(orth_dst, t);
        }
    }
}

// ---------------- SpMM float4, 4 rows per block, branch-free unroll-8 ----------------
__global__ void k_spmm(const float* __restrict__ H0, int src_id, int dst_id) {
    int rl = threadIdx.x >> 6, d4 = threadIdx.x & 63;
    int m = blockIdx.x * 4 + rl;
    __shared__ int   csh[4][MAXNZ];
    __shared__ float vsh[4][MAXNZ];
    int nzp = g_nnzp[m];
    for (int i = d4; i < nzp; i += 64) {
        csh[rl][i] = g_cols[m * MAXNZ + i];
        vsh[rl][i] = g_vals[m * MAXNZ + i];
    }
    __syncthreads();
    const float4* src = (const float4*)((src_id == 0) ? H0 : g_H1);
    float4 acc = make_float4(0.f, 0.f, 0.f, 0.f);
    for (int i = 0; i < nzp; i += 8) {
        float4 x0 = src[csh[rl][i    ] * 64 + d4];
        float4 x1 = src[csh[rl][i + 1] * 64 + d4];
        float4 x2 = src[csh[rl][i + 2] * 64 + d4];
        float4 x3 = src[csh[rl][i + 3] * 64 + d4];
        float4 x4 = src[csh[rl][i + 4] * 64 + d4];
        float4 x5 = src[csh[rl][i + 5] * 64 + d4];
        float4 x6 = src[csh[rl][i + 6] * 64 + d4];
        float4 x7 = src[csh[rl][i + 7] * 64 + d4];
        float v0 = vsh[rl][i],     v1 = vsh[rl][i + 1], v2 = vsh[rl][i + 2], v3 = vsh[rl][i + 3];
        float v4 = vsh[rl][i + 4], v5 = vsh[rl][i + 5], v6 = vsh[rl][i + 6], v7 = vsh[rl][i + 7];
        acc.x += v0*x0.x + v1*x1.x + v2*x2.x + v3*x3.x + v4*x4.x + v5*x5.x + v6*x6.x + v7*x7.x;
        acc.y += v0*x0.y + v1*x1.y + v2*x2.y + v3*x3.y + v4*x4.y + v5*x5.y + v6*x6.y + v7*x7.y;
        acc.z += v0*x0.z + v1*x1.z + v2*x2.z + v3*x3.z + v4*x4.z + v5*x5.z + v6*x6.z + v7*x7.z;
        acc.w += v0*x0.w + v1*x1.w + v2*x2.w + v3*x3.w + v4*x4.w + v5*x5.w + v6*x6.w + v7*x7.w;
    }
    float4* dst = (float4*)((dst_id == 1) ? g_H1 : g_H2);
    dst[m * 64 + d4] = acc;
}

// ---------------- fused: ZT tile GEMM + partial M (grid 32 x 3) ----------------
__global__ void k_ZM(const float* __restrict__ H0, const float* __restrict__ U) {
    __shared__ float Hs[128 * 33];
    __shared__ float Us[32][32];
    int kz = blockIdx.y;
    const float* src = (kz == 0) ? H0 : (kz == 1) ? g_H1 : g_H2;
    const float* Uk = U + kz * Dd * Rr;
    int n0 = blockIdx.x * 128;
    int tx = threadIdx.x & 15;
    int ty = threadIdx.x >> 4;
    float acc[8][2];
    #pragma unroll
    for (int q = 0; q < 8; q++) { acc[q][0] = 0.f; acc[q][1] = 0.f; }
    for (int d0 = 0; d0 < Dd; d0 += 32) {
        const float4* s4 = (const float4*)(src + (size_t)n0 * Dd + d0);
        int rr = threadIdx.x >> 3, cc = threadIdx.x & 7;
        #pragma unroll
        for (int q = 0; q < 4; q++) {
            float4 v = s4[(rr + q * 32) * 64 + cc];
            float* hp = &Hs[(rr + q * 32) * 33 + cc * 4];
            hp[0] = v.x; hp[1] = v.y; hp[2] = v.z; hp[3] = v.w;
        }
        int kk = threadIdx.x >> 3, c4 = threadIdx.x & 7;
        *(float4*)&Us[kk][c4 * 4] = *(const float4*)&Uk[(d0 + kk) * Rr + c4 * 4];
        __syncthreads();
        #pragma unroll
        for (int k2 = 0; k2 < 32; k2++) {
            float b0 = Us[k2][tx * 2], b1 = Us[k2][tx * 2 + 1];
            #pragma unroll
            for (int q = 0; q < 8; q++) {
                float a = Hs[(ty * 8 + q) * 33 + k2];
                acc[q][0] += a * b0; acc[q][1] += a * b1;
            }
        }
        __syncthreads();
    }
    #pragma unroll
    for (int q = 0; q < 8; q++) {
        int n = ty * 8 + q;
        *(float2*)&g_ZT[kz * Nn * Rr + (n0 + n) * Rr + tx * 2] = make_float2(acc[q][0], acc[q][1]);
        Hs[n * 33 + tx * 2] = acc[q][0];
        Hs[n * 33 + tx * 2 + 1] = acc[q][1];
    }
    __syncthreads();
    int i0 = (threadIdx.x >> 4) * 2, j0 = (threadIdx.x & 15) * 2;
    float a00 = 0.f, a01 = 0.f, a10 = 0.f, a11 = 0.f;
    #pragma unroll 4
    for (int n = 0; n < 128; n++) {
        float zi0 = Hs[n * 33 + i0], zi1 = Hs[n * 33 + i0 + 1];
        float zj0 = Hs[n * 33 + j0], zj1 = Hs[n * 33 + j0 + 1];
        a00 += zi0 * zj0; a01 += zi0 * zj1;
        a10 += zi1 * zj0; a11 += zi1 * zj1;
    }
    float* p = g_part + (kz * 32 + blockIdx.x) * Rr * Rr;
    p[i0 * 32 + j0] = a00; p[i0 * 32 + j0 + 1] = a01;
    p[(i0 + 1) * 32 + j0] = a10; p[(i0 + 1) * 32 + j0 + 1] = a11;
}

// ---------------- reduce + Cholesky + inverse (3 blocks of 1024) ----------------
__global__ void k_cholinv() {
    __shared__ float Msh[Rr * 33];
    __shared__ float ysh[Rr * 33];
    int kz = blockIdx.x;
    int tid = threadIdx.x;
    int i = tid >> 5, j = tid & 31;
    float s = 0.0f;
    #pragma unroll
    for (int b = 0; b < 32; b++) s += g_part[(kz * 32 + b) * Rr * Rr + tid];
    Msh[i * 33 + j] = COEFF * s + (i == j ? 1.0f : 0.0f);
    __syncthreads();
    for (int k2 = 0; k2 < Rr; k2++) {
        if (tid == 0) Msh[k2 * 33 + k2] = sqrtf(Msh[k2 * 33 + k2]);
        __syncthreads();
        if (j == k2 && i > k2) Msh[i * 33 + k2] /= Msh[k2 * 33 + k2];
        __syncthreads();
        if (i > k2 && j > k2 && j <= i) Msh[i * 33 + j] -= Msh[i * 33 + k2] * Msh[j * 33 + k2];
        __syncthreads();
    }
    int c = i, lane = j;
    for (int r = 0; r < Rr; r++) {
        float contrib = (lane < r) ? Msh[r * 33 + lane] * ysh[c * 33 + lane] : 0.0f;
        contrib = warp_sum(contrib);
        if (lane == 0) ysh[c * 33 + r] = (((r == c) ? 1.0f : 0.0f) - contrib) / Msh[r * 33 + r];
        __syncwarp();
    }
    for (int r = Rr - 1; r >= 0; r--) {
        float contrib = (lane > r) ? Msh[lane * 33 + r] * ysh[c * 33 + lane] : 0.0f;
        contrib = warp_sum(contrib);
        if (lane == 0) ysh[c * 33 + r] = (ysh[c * 33 + r] - contrib) / Msh[r * 33 + r];
        __syncwarp();
    }
    __syncthreads();
    g_Minv[kz * Rr * Rr + i * 32 + j] = ysh[j * 33 + i];
}

// ---------------- attention: smem-staged neighbors, lane-parallel scores ----------------
// FIX vs round 6: no __shfl_sync inside divergent code. qp is staged in smem and
// read back via broadcast LDS; score loop runs on ALL lanes, invalid lanes masked after.
__global__ void k_attn() {
    __shared__ float Mi[Rr * 33];
    __shared__ float zs[8][SN * 33];
    __shared__ float qs[8][Rr];
    __shared__ float ash[8][MAXNZ];
    int kz = blockIdx.y;
    int tid = threadIdx.x;
    for (int q = tid; q < Rr * Rr; q += 256)
        Mi[(q >> 5) * 33 + (q & 31)] = g_Minv[kz * Rr * Rr + q];
    __syncthreads();
    int w = tid >> 5, lane = tid & 31;
    int m = blockIdx.x * 8 + w;
    int nz = g_nnz[m];
    const int* cp = &g_cols[m * MAXNZ];
    const float* ZTk = g_ZT + kz * Nn * Rr;
    // preload neighbor columns into registers (uniform shfl broadcast later)
    int c0r = (lane < nz)      ? cp[lane]      : m;
    int c1r = (32 + lane < nz) ? cp[32 + lane] : m;
    int c2r = (64 + lane < nz) ? cp[64 + lane] : m;
    float z = ZTk[m * Rr + lane];
    // qp[s=lane] = sum_r z[r] * Minv[r][s]   (uniform shfl: all lanes execute)
    float qp = 0.0f;
    #pragma unroll
    for (int r = 0; r < Rr; r++)
        qp += Mi[r * 33 + lane] * __shfl_sync(0xFFFFFFFFu, z, r);
    qs[w][lane] = qp;
    int ns = (nz < SN) ? nz : SN;
    // stage neighbor z-vectors (coalesced, conflict-free: stride 33); uniform loop
    for (int i = 0; i < ns; i++) {
        int c = __shfl_sync(0xFFFFFFFFu, c0r, i);
        zs[w][i * 33 + lane] = ZTk[c * Rr + lane];
    }
    // zero unused staged slots so all-lane score compute is safe
    for (int i = ns; i < SN; i++) zs[w][i * 33 + lane] = 0.0f;
    __syncwarp();
    // lane-parallel scores: lane computes score of neighbor 'lane' (ALL lanes, no divergence)
    float s = 0.0f;
    #pragma unroll
    for (int s2 = 0; s2 < Rr; s2++)
        s += qs[w][s2] * zs[w][lane * 33 + s2];
    float sc0 = (lane < ns) ? s : -1e30f;
    // fallback scores for i >= SN (uniform loop; warp_sum shfl is all-lane)
    for (int i = SN; i < nz; i++) {
        int c = __shfl_sync(0xFFFFFFFFu, (i < 64) ? c1r : c2r, i & 31);
        float p = warp_sum(qp * ZTk[c * Rr + lane]);
        if (lane == 0) ash[w][i] = p;
    }
    __syncwarp();
    // softmax
    float mx = sc0;
    for (int i = SN + lane; i < nz; i += 32) mx = fmaxf(mx, ash[w][i]);
    mx = warp_max(mx);
    float e0 = (lane < ns) ? expf(sc0 - mx) : 0.0f;
    float sm = e0;
    for (int i = SN + lane; i < nz; i += 32) {
        float e = expf(ash[w][i] - mx);
        ash[w][i] = e; sm += e;
    }
    sm = warp_sum(sm);
    float inv = 1.0f / sm;
    ash[w][lane] = e0;   // lanes >= ns write 0 into slots ns..31 (harmless: zs there is 0)
    __syncwarp();
    // t[r=lane] = sum_i alpha_i * z_i[r]
    float t = 0.0f;
    for (int i = 0; i < ns; i++)
        t += ash[w][i] * zs[w][i * 33 + lane];
    for (int i = SN; i < nz; i++) {
        int c = __shfl_sync(0xFFFFFFFFu, (i < 64) ? c1r : c2r, i & 31);
        t += ash[w][i] * ZTk[c * Rr + lane];
    }
    t *= inv;
    // out[r=lane] = sum_s Minv[r][s] * t[s]   (uniform shfl)
    float o = 0.0f;
    #pragma unroll
    for (int s2 = 0; s2 < Rr; s2++)
        o += Mi[lane * 33 + s2] * __shfl_sync(0xFFFFFFFFu, t, s2);
    g_Gcat[m * (Kk * Rr) + kz * Rr + lane] = o * (ETA * g_w[kz]);
}

// ---------------- fused: agg GEMM + H3 gather + threshold + residual + LN ----------------
// grid 128, block 256: 32 rows x 256 cols per block; thread: 8 rows x 4 cols
__global__ void k_gf(const float* __restrict__ H0, const float* __restrict__ U,
                     const float* __restrict__ thr, const float* __restrict__ gam,
                     const float* __restrict__ bet, float* __restrict__ out) {
    __shared__ float Us[32 * 260];   // [r][d], pad 260
    __shared__ float Gs[32 * 33];    // [row][r-chunk]
    __shared__ float red[8][8][2];   // [warp][q][s1,s2]
    int tid = threadIdx.x;
    int ty = tid >> 6, tx = tid & 63;
    int n0 = blockIdx.x * 32;
    float acc[8][4];
    #pragma unroll
    for (int q = 0; q < 8; q++) { acc[q][0] = 0.f; acc[q][1] = 0.f; acc[q][2] = 0.f; acc[q][3] = 0.f; }
    for (int k = 0; k < Kk; k++) {
        __syncthreads();
        for (int q = tid; q < 32 * 32; q += 256) {
            int row = q >> 5, r = q & 31;
            Gs[row * 33 + r] = g_Gcat[(n0 + row) * (Kk * Rr) + k * Rr + r];
        }
        #pragma unroll
        for (int q = 0; q < 32; q++) {
            int lin = tid + q * 256;
            int d = lin >> 5, r = lin & 31;
            Us[r * 260 + d] = U[k * Dd * Rr + d * Rr + r];
        }
        __syncthreads();
        #pragma unroll
        for (int r = 0; r < Rr; r++) {
            float4 b4 = *(float4*)&Us[r * 260 + tx * 4];
            #pragma unroll
            for (int q2 = 0; q2 < 8; q2++) {
                float a = Gs[(ty * 8 + q2) * 33 + r];
                acc[q2][0] += a * b4.x; acc[q2][1] += a * b4.y;
                acc[q2][2] += a * b4.z; acc[q2][3] += a * b4.w;
            }
        }
    }
    // epilogue
    const float4* H0_4 = (const float4*)H0;
    const float4* H1_4 = (const float4*)g_H1;
    const float4* H2_4 = (const float4*)g_H2;
    float l0 = g_lap[0], l1 = g_lap[1], l2 = g_lap[2];
    float4 t4 = ((const float4*)thr)[tx];
    int wp = tid >> 5;
    #pragma unroll
    for (int q2 = 0; q2 < 8; q2++) {
        int m = n0 + ty * 8 + q2;
        int idx4 = m * 64 + tx;
        float4 x  = H0_4[idx4];
        float4 h1 = H1_4[idx4];
        float4 h2 = H2_4[idx4];
        float4 h3 = make_float4(0.f, 0.f, 0.f, 0.f);
        int nzp = g_nnzp[m];
        const int*   cpm = &g_cols[m * MAXNZ];
        const float* vpm = &g_vals[m * MAXNZ];
        for (int i = 0; i < nzp; i += 4) {
            int   cA = cpm[i],     cB = cpm[i + 1], cC = cpm[i + 2], cD = cpm[i + 3];
            float vA = vpm[i],     vB = vpm[i + 1], vC = vpm[i + 2], vD = vpm[i + 3];
            float4 xA = H2_4[cA * 64 + tx];
            float4 xB = H2_4[cB * 64 + tx];
            float4 xC = H2_4[cC * 64 + tx];
            float4 xD = H2_4[cD * 64 + tx];
            h3.x += vA*xA.x + vB*xB.x + vC*xC.x + vD*xD.x;
            h3.y += vA*xA.y + vB*xB.y + vC*xC.y + vD*xD.y;
            h3.z += vA*xA.z + vB*xB.z + vC*xC.z + vD*xD.z;
            h3.w += vA*xA.w + vB*xB.w + vC*xC.w + vD*xD.w;
        }
        float xs[4] = {x.x, x.y, x.z, x.w};
        float a1[4] = {h1.x, h1.y, h1.z, h1.w};
        float a2[4] = {h2.x, h2.y, h2.z, h2.w};
        float a3[4] = {h3.x, h3.y, h3.z, h3.w};
        float ts[4] = {t4.x, t4.y, t4.z, t4.w};
        float s1 = 0.f, s2s = 0.f;
        #pragma unroll
        for (int c = 0; c < 4; c++) {
            float lap = l0 * (xs[c] - a1[c]) + l1 * (a1[c] - a2[c]) + l2 * (a2[c] - a3[c]);
            float h = xs[c] + acc[q2][c] - ETA * lap;
            float a = fabsf(h) - ts[c];
            float yv = (a > 0.0f) ? copysignf(a, h) : 0.0f;
            yv += xs[c];
            acc[q2][c] = yv;            // y stored in place
            s1 += yv; s2s += yv * yv;
        }
        s1 = warp_sum(s1); s2s = warp_sum(s2s);
        if ((tid & 31) == 0) { red[wp][q2][0] = s1; red[wp][q2][1] = s2s; }
    }
    __syncthreads();
    float4 g4 = ((const float4*)gam)[tx];
    float4 b4 = ((const float4*)bet)[tx];
    #pragma unroll
    for (int q2 = 0; q2 < 8; q2++) {
        int m = n0 + ty * 8 + q2;
        float mu  = (red[ty * 2][q2][0] + red[ty * 2 + 1][q2][0]) * (1.0f / Dd);
        float ex2 = (red[ty * 2][q2][1] + red[ty * 2 + 1][q2][1]) * (1.0f / Dd);
        float inv_sd = rsqrtf(ex2 - mu * mu + LN_EPS);
        float4 o4;
        o4.x = (acc[q2][0] - mu) * inv_sd * g4.x + b4.x;
        o4.y = (acc[q2][1] - mu) * inv_sd * g4.y + b4.y;
        o4.z = (acc[q2][2] - mu) * inv_sd * g4.z + b4.z;
        o4.w = (acc[q2][3] - mu) * inv_sd * g4.w + b4.w;
        ((float4*)out)[m * 64 + tx] = o4;
    }
}

// ---------------- lap_smooth = sum(H_out * (H_out - A@H_out)); 4 rows/block ----------------
__global__ void k_lapsm(const float* __restrict__ out, float* __restrict__ dst) {
    int rl = threadIdx.x >> 6, t64 = threadIdx.x & 63;
    int m = blockIdx.x * 4 + rl;
    __shared__ int   csh[4][MAXNZ];
    __shared__ float vsh[4][MAXNZ];
    __shared__ float wred[8];
    int nzp = g_nnzp[m];
    for (int i = t64; i < nzp; i += 64) {
        csh[rl][i] = g_cols[m * MAXNZ + i];
        vsh[rl][i] = g_vals[m * MAXNZ + i];
    }
    __syncthreads();
    const float4* o4 = (const float4*)out;
    float4 o = o4[m * 64 + t64];
    float4 ah = make_float4(0.f, 0.f, 0.f, 0.f);
    for (int i = 0; i < nzp; i += 4) {
        float4 x0 = o4[csh[rl][i]     * 64 + t64];
        float4 x1 = o4[csh[rl][i + 1] * 64 + t64];
        float4 x2 = o4[csh[rl][i + 2] * 64 + t64];
        float4 x3 = o4[csh[rl][i + 3] * 64 + t64];
        float v0 = vsh[rl][i], v1 = vsh[rl][i + 1], v2 = vsh[rl][i + 2], v3 = vsh[rl][i + 3];
        ah.x += v0*x0.x + v1*x1.x + v2*x2.x + v3*x3.x;
        ah.y += v0*x0.y + v1*x1.y + v2*x2.y + v3*x3.y;
        ah.z += v0*x0.z + v1*x1.z + v2*x2.z + v3*x3.z;
        ah.w += v0*x0.w + v1*x1.w + v2*x2.w + v3*x3.w;
    }
    float part = o.x * (o.x - ah.x) + o.y * (o.y - ah.y) + o.z * (o.z - ah.z) + o.w * (o.w - ah.w);
    int w = threadIdx.x >> 5, lane = threadIdx.x & 31;
    float s = warp_sum(part);
    if (lane == 0) wred[w] = s;
    __syncthreads();
    if (threadIdx.x == 0) {
        float t = 0.0f;
        #pragma unroll
        for (int q = 0; q < 8; q++) t += wred[q];
        atomicAdd(dst, t);
    }
}

// ---------------- launch ----------------
extern "C" void kernel_launch(void* const* d_in, const int* in_sizes, int n_in,
                              void* d_out, int out_size) {
    const float* H   = (const float*)d_in[0];
    const float* A   = (const float*)d_in[1];
    const float* U   = (const float*)d_in[4];
    const float* lam = (const float*)d_in[5];
    const float* hw  = (const float*)d_in[6];
    const float* thr = (const float*)d_in[7];
    const float* gam = (const float*)d_in[8];
    const float* bet = (const float*)d_in[9];
    float* out  = (float*)d_out;
    float* tail = out + (size_t)Nn * Dd;   // [orth, lap_smooth, w0, w1, w2]

    k_setup<<<1, 32>>>(lam, hw, tail);
    k_csr_orth<<<518, 256>>>(A, U, tail + 0);

    k_spmm<<<Nn / 4, 256>>>(H, 0, 1);   // H1 = A @ H
    k_spmm<<<Nn / 4, 256>>>(H, 1, 2);   // H2 = A @ H1

    k_ZM<<<dim3(32, Kk), 256>>>(H, U);  // ZT + partial M, fused
    k_cholinv<<<Kk, 1024>>>();
    k_attn<<<dim3(Nn / 8, Kk), 256>>>();

    k_gf<<<Nn / 32, 256>>>(H, U, thr, gam, bet, out);  // agg GEMM + finalize fused
    k_lapsm<<<Nn / 4, 256>>>(out, tail + 1);
}

// round 9
// speedup vs baseline: 1.0154x; 1.0154x over previous
#include <cuda_runtime.h>
#include <math.h>

#define Nn 4096
#define Dd 256
#define Rr 32
#define Kk 3
#define MAXNZ 96
#define SN 32                   /* staged neighbors in attn (fallback beyond) */
#define ETA 0.5f
#define COEFF 0.03125f          /* r/(n*eps^2) = 32/(4096*0.25) */
#define LN_EPS 1e-5f

// ---------------- device scratch ----------------
__device__ float g_H1[Nn*Dd];
__device__ float g_H2[Nn*Dd];
__device__ float g_ZT[Kk*Nn*Rr];       // [k][n][r]
__device__ float g_part[Kk*32*Rr*Rr];  // [k][chunk][32*32]
__device__ float g_Minv[Kk*Rr*Rr];
__device__ float g_Gcat[Nn*Kk*Rr];     // [n][k*32+r], pre-scaled by ETA*w_k
__device__ float g_agg[Nn*Dd];
__device__ int   g_nnz[Nn];            // true count
__device__ int   g_nnzp[Nn];           // padded to multiple of 8 (pad: col=row, val=0)
__device__ int   g_cols[Nn*MAXNZ];
__device__ float g_vals[Nn*MAXNZ];
__device__ float g_w[Kk];
__device__ float g_lap[Kk];

__device__ __forceinline__ float warp_sum(float v) {
    #pragma unroll
    for (int o = 16; o; o >>= 1) v += __shfl_xor_sync(0xFFFFFFFFu, v, o);
    return v;
}
__device__ __forceinline__ float warp_max(float v) {
    #pragma unroll
    for (int o = 16; o; o >>= 1) v = fmaxf(v, __shfl_xor_sync(0xFFFFFFFFu, v, o));
    return v;
}

// ---------------- setup ----------------
__global__ void k_setup(const float* lam, const float* hw, float* tail) {
    if (threadIdx.x == 0) {
        float h0 = hw[0], h1 = hw[1], h2 = hw[2];
        float mx = fmaxf(h0, fmaxf(h1, h2));
        float e0 = expf(h0 - mx), e1 = expf(h1 - mx), e2 = expf(h2 - mx);
        float inv = 1.0f / (e0 + e1 + e2);
        g_w[0] = e0 * inv; g_w[1] = e1 * inv; g_w[2] = e2 * inv;
        for (int k = 0; k < Kk; k++) g_lap[k] = log1pf(expf(lam[k]));
        tail[0] = 0.0f; tail[1] = 0.0f;
        tail[2] = g_w[0]; tail[3] = g_w[1]; tail[4] = g_w[2];
    }
}

// ---------------- CSR extraction (blocks 0..511) + orth loss (blocks 512..517) ----------------
__global__ void k_csr_orth(const float* __restrict__ A, const float* __restrict__ U,
                           float* __restrict__ orth_dst) {
    if (blockIdx.x < 512) {
        int warp = threadIdx.x >> 5, lane = threadIdx.x & 31;
        int row = blockIdx.x * 8 + warp;
        const float4* ar = (const float4*)(A + (size_t)row * Nn);
        unsigned mlt = (1u << lane) - 1u;
        int base = 0;
        for (int c0 = 0; c0 < Nn / 4; c0 += 32) {
            float4 v = ar[c0 + lane];
            unsigned b0 = __ballot_sync(0xFFFFFFFFu, v.x != 0.0f);
            unsigned b1 = __ballot_sync(0xFFFFFFFFu, v.y != 0.0f);
            unsigned b2 = __ballot_sync(0xFFFFFFFFu, v.z != 0.0f);
            unsigned b3 = __ballot_sync(0xFFFFFFFFu, v.w != 0.0f);
            int pos = base + __popc(b0 & mlt) + __popc(b1 & mlt)
                           + __popc(b2 & mlt) + __popc(b3 & mlt);
            int cbase = (c0 + lane) * 4;
            if (v.x != 0.0f && pos < MAXNZ) { g_cols[row*MAXNZ+pos] = cbase;     g_vals[row*MAXNZ+pos] = v.x; pos++; }
            if (v.y != 0.0f && pos < MAXNZ) { g_cols[row*MAXNZ+pos] = cbase + 1; g_vals[row*MAXNZ+pos] = v.y; pos++; }
            if (v.z != 0.0f && pos < MAXNZ) { g_cols[row*MAXNZ+pos] = cbase + 2; g_vals[row*MAXNZ+pos] = v.z; pos++; }
            if (v.w != 0.0f && pos < MAXNZ) { g_cols[row*MAXNZ+pos] = cbase + 3; g_vals[row*MAXNZ+pos] = v.w; pos++; }
            base += __popc(b0) + __popc(b1) + __popc(b2) + __popc(b3);
        }
        if (base > MAXNZ) base = MAXNZ;
        int padded = (base + 7) & ~7;
        if (padded > MAXNZ) padded = MAXNZ;
        for (int i = base + lane; i < padded; i += 32) {
            g_cols[row * MAXNZ + i] = row;
            g_vals[row * MAXNZ + i] = 0.0f;
        }
        if (lane == 0) { g_nnz[row] = base; g_nnzp[row] = padded; }
    } else {
        const int pk[6] = {0,0,0,1,1,2}, pl[6] = {0,1,2,1,2,2};
        int p = blockIdx.x - 512;
        int k = pk[p], l = pl[p];
        int ab = threadIdx.x >> 5, b = threadIdx.x & 31;
        const float* Ua = U + k * Dd * Rr;
        const float* Ub = U + l * Dd * Rr;
        float tot = 0.0f;
        for (int ao = 0; ao < 4; ao++) {
            int a = ao * 8 + ab;
            float g = 0.0f;
            #pragma unroll 8
            for (int d = 0; d < Dd; d++) g += Ua[d * Rr + a] * Ub[d * Rr + b];
            if (k == l && a == b) g -= 1.0f;
            tot += g * g;
        }
        __shared__ float wred[8];
        int w = threadIdx.x >> 5, lane = threadIdx.x & 31;
        float s = warp_sum(tot);
        if (lane == 0) wred[w] = s;
        __syncthreads();
        if (threadIdx.x == 0) {
            float t = 0.0f;
            #pragma unroll
            for (int q = 0; q < 8; q++) t += wred[q];
            atomicAdd(orth_dst, t);
        }
    }
}

// ---------------- SpMM float4, 4 rows per block, branch-free unroll-8 ----------------
__global__ void k_spmm(const float* __restrict__ H0, int src_id, int dst_id) {
    int rl = threadIdx.x >> 6, d4 = threadIdx.x & 63;
    int m = blockIdx.x * 4 + rl;
    __shared__ int   csh[4][MAXNZ];
    __shared__ float vsh[4][MAXNZ];
    int nzp = g_nnzp[m];
    for (int i = d4; i < nzp; i += 64) {
        csh[rl][i] = g_cols[m * MAXNZ + i];
        vsh[rl][i] = g_vals[m * MAXNZ + i];
    }
    __syncthreads();
    const float4* src = (const float4*)((src_id == 0) ? H0 : g_H1);
    float4 acc = make_float4(0.f, 0.f, 0.f, 0.f);
    for (int i = 0; i < nzp; i += 8) {
        float4 x0 = src[csh[rl][i    ] * 64 + d4];
        float4 x1 = src[csh[rl][i + 1] * 64 + d4];
        float4 x2 = src[csh[rl][i + 2] * 64 + d4];
        float4 x3 = src[csh[rl][i + 3] * 64 + d4];
        float4 x4 = src[csh[rl][i + 4] * 64 + d4];
        float4 x5 = src[csh[rl][i + 5] * 64 + d4];
        float4 x6 = src[csh[rl][i + 6] * 64 + d4];
        float4 x7 = src[csh[rl][i + 7] * 64 + d4];
        float v0 = vsh[rl][i],     v1 = vsh[rl][i + 1], v2 = vsh[rl][i + 2], v3 = vsh[rl][i + 3];
        float v4 = vsh[rl][i + 4], v5 = vsh[rl][i + 5], v6 = vsh[rl][i + 6], v7 = vsh[rl][i + 7];
        acc.x += v0*x0.x + v1*x1.x + v2*x2.x + v3*x3.x + v4*x4.x + v5*x5.x + v6*x6.x + v7*x7.x;
        acc.y += v0*x0.y + v1*x1.y + v2*x2.y + v3*x3.y + v4*x4.y + v5*x5.y + v6*x6.y + v7*x7.y;
        acc.z += v0*x0.z + v1*x1.z + v2*x2.z + v3*x3.z + v4*x4.z + v5*x5.z + v6*x6.z + v7*x7.z;
        acc.w += v0*x0.w + v1*x1.w + v2*x2.w + v3*x3.w + v4*x4.w + v5*x5.w + v6*x6.w + v7*x7.w;
    }
    float4* dst = (float4*)((dst_id == 1) ? g_H1 : g_H2);
    dst[m * 64 + d4] = acc;
}

// ---------------- fused: ZT tile GEMM + partial M (grid 32 x 3) ----------------
__global__ void k_ZM(const float* __restrict__ H0, const float* __restrict__ U) {
    __shared__ float Hs[128 * 33];
    __shared__ float Us[32][32];
    int kz = blockIdx.y;
    const float* src = (kz == 0) ? H0 : (kz == 1) ? g_H1 : g_H2;
    const float* Uk = U + kz * Dd * Rr;
    int n0 = blockIdx.x * 128;
    int tx = threadIdx.x & 15;
    int ty = threadIdx.x >> 4;
    float acc[8][2];
    #pragma unroll
    for (int q = 0; q < 8; q++) { acc[q][0] = 0.f; acc[q][1] = 0.f; }
    for (int d0 = 0; d0 < Dd; d0 += 32) {
        const float4* s4 = (const float4*)(src + (size_t)n0 * Dd + d0);
        int rr = threadIdx.x >> 3, cc = threadIdx.x & 7;
        #pragma unroll
        for (int q = 0; q < 4; q++) {
            float4 v = s4[(rr + q * 32) * 64 + cc];
            float* hp = &Hs[(rr + q * 32) * 33 + cc * 4];
            hp[0] = v.x; hp[1] = v.y; hp[2] = v.z; hp[3] = v.w;
        }
        int kk = threadIdx.x >> 3, c4 = threadIdx.x & 7;
        *(float4*)&Us[kk][c4 * 4] = *(const float4*)&Uk[(d0 + kk) * Rr + c4 * 4];
        __syncthreads();
        #pragma unroll
        for (int k2 = 0; k2 < 32; k2++) {
            float b0 = Us[k2][tx * 2], b1 = Us[k2][tx * 2 + 1];
            #pragma unroll
            for (int q = 0; q < 8; q++) {
                float a = Hs[(ty * 8 + q) * 33 + k2];
                acc[q][0] += a * b0; acc[q][1] += a * b1;
            }
        }
        __syncthreads();
    }
    #pragma unroll
    for (int q = 0; q < 8; q++) {
        int n = ty * 8 + q;
        *(float2*)&g_ZT[kz * Nn * Rr + (n0 + n) * Rr + tx * 2] = make_float2(acc[q][0], acc[q][1]);
        Hs[n * 33 + tx * 2] = acc[q][0];
        Hs[n * 33 + tx * 2 + 1] = acc[q][1];
    }
    __syncthreads();
    int i0 = (threadIdx.x >> 4) * 2, j0 = (threadIdx.x & 15) * 2;
    float a00 = 0.f, a01 = 0.f, a10 = 0.f, a11 = 0.f;
    #pragma unroll 4
    for (int n = 0; n < 128; n++) {
        float zi0 = Hs[n * 33 + i0], zi1 = Hs[n * 33 + i0 + 1];
        float zj0 = Hs[n * 33 + j0], zj1 = Hs[n * 33 + j0 + 1];
        a00 += zi0 * zj0; a01 += zi0 * zj1;
        a10 += zi1 * zj0; a11 += zi1 * zj1;
    }
    float* p = g_part + (kz * 32 + blockIdx.x) * Rr * Rr;
    p[i0 * 32 + j0] = a00; p[i0 * 32 + j0 + 1] = a01;
    p[(i0 + 1) * 32 + j0] = a10; p[(i0 + 1) * 32 + j0 + 1] = a11;
}

// ---------------- reduce + Cholesky + inverse (3 blocks of 1024) ----------------
__global__ void k_cholinv() {
    __shared__ float Msh[Rr * 33];
    __shared__ float ysh[Rr * 33];
    int kz = blockIdx.x;
    int tid = threadIdx.x;
    int i = tid >> 5, j = tid & 31;
    float s = 0.0f;
    #pragma unroll
    for (int b = 0; b < 32; b++) s += g_part[(kz * 32 + b) * Rr * Rr + tid];
    Msh[i * 33 + j] = COEFF * s + (i == j ? 1.0f : 0.0f);
    __syncthreads();
    for (int k2 = 0; k2 < Rr; k2++) {
        if (tid == 0) Msh[k2 * 33 + k2] = sqrtf(Msh[k2 * 33 + k2]);
        __syncthreads();
        if (j == k2 && i > k2) Msh[i * 33 + k2] /= Msh[k2 * 33 + k2];
        __syncthreads();
        if (i > k2 && j > k2 && j <= i) Msh[i * 33 + j] -= Msh[i * 33 + k2] * Msh[j * 33 + k2];
        __syncthreads();
    }
    int c = i, lane = j;
    for (int r = 0; r < Rr; r++) {
        float contrib = (lane < r) ? Msh[r * 33 + lane] * ysh[c * 33 + lane] : 0.0f;
        contrib = warp_sum(contrib);
        if (lane == 0) ysh[c * 33 + r] = (((r == c) ? 1.0f : 0.0f) - contrib) / Msh[r * 33 + r];
        __syncwarp();
    }
    for (int r = Rr - 1; r >= 0; r--) {
        float contrib = (lane > r) ? Msh[lane * 33 + r] * ysh[c * 33 + lane] : 0.0f;
        contrib = warp_sum(contrib);
        if (lane == 0) ysh[c * 33 + r] = (ysh[c * 33 + r] - contrib) / Msh[r * 33 + r];
        __syncwarp();
    }
    __syncthreads();
    g_Minv[kz * Rr * Rr + i * 32 + j] = ysh[j * 33 + i];
}

// ---------------- attention: smem-staged neighbors, lane-parallel scores ----------------
__global__ void k_attn() {
    __shared__ float Mi[Rr * 33];
    __shared__ float zs[8][SN * 33];
    __shared__ float qs[8][Rr];
    __shared__ float ash[8][MAXNZ];
    int kz = blockIdx.y;
    int tid = threadIdx.x;
    for (int q = tid; q < Rr * Rr; q += 256)
        Mi[(q >> 5) * 33 + (q & 31)] = g_Minv[kz * Rr * Rr + q];
    __syncthreads();
    int w = tid >> 5, lane = tid & 31;
    int m = blockIdx.x * 8 + w;
    int nz = g_nnz[m];
    const int* cp = &g_cols[m * MAXNZ];
    const float* ZTk = g_ZT + kz * Nn * Rr;
    int c0r = (lane < nz)      ? cp[lane]      : m;
    int c1r = (32 + lane < nz) ? cp[32 + lane] : m;
    int c2r = (64 + lane < nz) ? cp[64 + lane] : m;
    float z = ZTk[m * Rr + lane];
    // qp[s=lane] = sum_r z[r] * Minv[r][s]   (uniform shfl: all lanes execute)
    float qp = 0.0f;
    #pragma unroll
    for (int r = 0; r < Rr; r++)
        qp += Mi[r * 33 + lane] * __shfl_sync(0xFFFFFFFFu, z, r);
    qs[w][lane] = qp;
    int ns = (nz < SN) ? nz : SN;
    for (int i = 0; i < ns; i++) {
        int c = __shfl_sync(0xFFFFFFFFu, c0r, i);
        zs[w][i * 33 + lane] = ZTk[c * Rr + lane];
    }
    for (int i = ns; i < SN; i++) zs[w][i * 33 + lane] = 0.0f;
    __syncwarp();
    // lane-parallel scores on ALL lanes, masked after
    float s = 0.0f;
    #pragma unroll
    for (int s2 = 0; s2 < Rr; s2++)
        s += qs[w][s2] * zs[w][lane * 33 + s2];
    float sc0 = (lane < ns) ? s : -1e30f;
    for (int i = SN; i < nz; i++) {
        int c = __shfl_sync(0xFFFFFFFFu, (i < 64) ? c1r : c2r, i & 31);
        float p = warp_sum(qp * ZTk[c * Rr + lane]);
        if (lane == 0) ash[w][i] = p;
    }
    __syncwarp();
    float mx = sc0;
    for (int i = SN + lane; i < nz; i += 32) mx = fmaxf(mx, ash[w][i]);
    mx = warp_max(mx);
    float e0 = (lane < ns) ? expf(sc0 - mx) : 0.0f;
    float sm = e0;
    for (int i = SN + lane; i < nz; i += 32) {
        float e = expf(ash[w][i] - mx);
        ash[w][i] = e; sm += e;
    }
    sm = warp_sum(sm);
    float inv = 1.0f / sm;
    ash[w][lane] = e0;
    __syncwarp();
    float t = 0.0f;
    for (int i = 0; i < ns; i++)
        t += ash[w][i] * zs[w][i * 33 + lane];
    for (int i = SN; i < nz; i++) {
        int c = __shfl_sync(0xFFFFFFFFu, (i < 64) ? c1r : c2r, i & 31);
        t += ash[w][i] * ZTk[c * Rr + lane];
    }
    t *= inv;
    float o = 0.0f;
    #pragma unroll
    for (int s2 = 0; s2 < Rr; s2++)
        o += Mi[lane * 33 + s2] * __shfl_sync(0xFFFFFFFFu, t, s2);
    g_Gcat[m * (Kk * Rr) + kz * Rr + lane] = o * (ETA * g_w[kz]);
}

// ---------------- agg = Gcat @ Ucat: tiled 64x64, 4x4 per thread ----------------
__global__ void k_gemm(const float* __restrict__ U) {
    __shared__ float Gs[64][33];
    __shared__ float Us[32][65];
    int n0 = blockIdx.x * 64, d0 = blockIdx.y * 64;
    int tx = threadIdx.x & 15, ty = threadIdx.x >> 4;
    float acc[4][4];
    #pragma unroll
    for (int a = 0; a < 4; a++)
        #pragma unroll
        for (int b = 0; b < 4; b++) acc[a][b] = 0.f;
    for (int k = 0; k < Kk; k++) {
        __syncthreads();
        #pragma unroll
        for (int q = 0; q < 8; q++) {
            int idx = threadIdx.x + 256 * q;
            int gi = idx >> 5, gr = idx & 31;
            Gs[gi][gr] = g_Gcat[(n0 + gi) * (Kk * Rr) + k * Rr + gr];
            Us[gr][gi] = U[k * Dd * Rr + (d0 + gi) * Rr + gr];
        }
        __syncthreads();
        #pragma unroll
        for (int r = 0; r < Rr; r++) {
            float a[4], b[4];
            #pragma unroll
            for (int q = 0; q < 4; q++) a[q] = Gs[ty * 4 + q][r];
            #pragma unroll
            for (int p = 0; p < 4; p++) b[p] = Us[r][tx * 4 + p];
            #pragma unroll
            for (int q = 0; q < 4; q++)
                #pragma unroll
                for (int p = 0; p < 4; p++) acc[q][p] += a[q] * b[p];
        }
    }
    #pragma unroll
    for (int q = 0; q < 4; q++) {
        float4 v = make_float4(acc[q][0], acc[q][1], acc[q][2], acc[q][3]);
        *(float4*)&g_agg[(size_t)(n0 + ty * 4 + q) * Dd + d0 + tx * 4] = v;
    }
}

// ---------------- finalize: inline H3 gather + threshold + residual + LN; 4 rows/block ----------------
__global__ void k_finalize(const float* __restrict__ H0, const float* __restrict__ thr,
                           const float* __restrict__ gam, const float* __restrict__ bet,
                           float* __restrict__ out) {
    int rl = threadIdx.x >> 6, t64 = threadIdx.x & 63;
    int m = blockIdx.x * 4 + rl;
    __shared__ int   csh[4][MAXNZ];
    __shared__ float vsh[4][MAXNZ];
    __shared__ float wred[8][2];
    int nzp = g_nnzp[m];
    for (int i = t64; i < nzp; i += 64) {
        csh[rl][i] = g_cols[m * MAXNZ + i];
        vsh[rl][i] = g_vals[m * MAXNZ + i];
    }
    __syncthreads();
    const float4* H0_4 = (const float4*)H0;
    const float4* H1_4 = (const float4*)g_H1;
    const float4* H2_4 = (const float4*)g_H2;
    const float4* ag4  = (const float4*)g_agg;
    int idx4 = m * 64 + t64;
    float4 x  = H0_4[idx4];
    float4 h1 = H1_4[idx4];
    float4 h2 = H2_4[idx4];
    float4 ag = ag4[idx4];
    float4 h3 = make_float4(0.f, 0.f, 0.f, 0.f);
    for (int i = 0; i < nzp; i += 4) {
        float4 x0 = H2_4[csh[rl][i]     * 64 + t64];
        float4 x1 = H2_4[csh[rl][i + 1] * 64 + t64];
        float4 x2 = H2_4[csh[rl][i + 2] * 64 + t64];
        float4 x3 = H2_4[csh[rl][i + 3] * 64 + t64];
        float v0 = vsh[rl][i], v1 = vsh[rl][i + 1], v2 = vsh[rl][i + 2], v3 = vsh[rl][i + 3];
        h3.x += v0*x0.x + v1*x1.x + v2*x2.x + v3*x3.x;
        h3.y += v0*x0.y + v1*x1.y + v2*x2.y + v3*x3.y;
        h3.z += v0*x0.z + v1*x1.z + v2*x2.z + v3*x3.z;
        h3.w += v0*x0.w + v1*x1.w + v2*x2.w + v3*x3.w;
    }
    float l0 = g_lap[0], l1 = g_lap[1], l2 = g_lap[2];
    float4 t4 = ((const float4*)thr)[t64];
    float y[4];
    {
        float xs[4] = {x.x, x.y, x.z, x.w};
        float a1[4] = {h1.x, h1.y, h1.z, h1.w};
        float a2[4] = {h2.x, h2.y, h2.z, h2.w};
        float a3[4] = {h3.x, h3.y, h3.z, h3.w};
        float ags[4] = {ag.x, ag.y, ag.z, ag.w};
        float ts[4] = {t4.x, t4.y, t4.z, t4.w};
        #pragma unroll
        for (int q = 0; q < 4; q++) {
            float lap = l0 * (xs[q] - a1[q]) + l1 * (a1[q] - a2[q]) + l2 * (a2[q] - a3[q]);
            float h = xs[q] + ags[q] - ETA * lap;
            float a = fabsf(h) - ts[q];
            float yv = (a > 0.0f) ? copysignf(a, h) : 0.0f;
            y[q] = yv + xs[q];
        }
    }
    float s1 = y[0] + y[1] + y[2] + y[3];
    float s2 = y[0]*y[0] + y[1]*y[1] + y[2]*y[2] + y[3]*y[3];
    s1 = warp_sum(s1); s2 = warp_sum(s2);
    int w = threadIdx.x >> 5, lane = threadIdx.x & 31;
    if (lane == 0) { wred[w][0] = s1; wred[w][1] = s2; }
    __syncthreads();
    float mu  = (wred[rl*2][0] + wred[rl*2+1][0]) * (1.0f / Dd);
    float ex2 = (wred[rl*2][1] + wred[rl*2+1][1]) * (1.0f / Dd);
    float inv_sd = rsqrtf(ex2 - mu * mu + LN_EPS);
    float4 g4 = ((const float4*)gam)[t64];
    float4 b4 = ((const float4*)bet)[t64];
    float4 o4;
    o4.x = (y[0] - mu) * inv_sd * g4.x + b4.x;
    o4.y = (y[1] - mu) * inv_sd * g4.y + b4.y;
    o4.z = (y[2] - mu) * inv_sd * g4.z + b4.z;
    o4.w = (y[3] - mu) * inv_sd * g4.w + b4.w;
    ((float4*)out)[idx4] = o4;
}

// ---------------- lap_smooth = sum(H_out * (H_out - A@H_out)); 4 rows/block ----------------
__global__ void k_lapsm(const float* __restrict__ out, float* __restrict__ dst) {
    int rl = threadIdx.x >> 6, t64 = threadIdx.x & 63;
    int m = blockIdx.x * 4 + rl;
    __shared__ int   csh[4][MAXNZ];
    __shared__ float vsh[4][MAXNZ];
    __shared__ float wred[8];
    int nzp = g_nnzp[m];
    for (int i = t64; i < nzp; i += 64) {
        csh[rl][i] = g_cols[m * MAXNZ + i];
        vsh[rl][i] = g_vals[m * MAXNZ + i];
    }
    __syncthreads();
    const float4* o4 = (const float4*)out;
    float4 o = o4[m * 64 + t64];
    float4 ah = make_float4(0.f, 0.f, 0.f, 0.f);
    for (int i = 0; i < nzp; i += 4) {
        float4 x0 = o4[csh[rl][i]     * 64 + t64];
        float4 x1 = o4[csh[rl][i + 1] * 64 + t64];
        float4 x2 = o4[csh[rl][i + 2] * 64 + t64];
        float4 x3 = o4[csh[rl][i + 3] * 64 + t64];
        float v0 = vsh[rl][i], v1 = vsh[rl][i + 1], v2 = vsh[rl][i + 2], v3 = vsh[rl][i + 3];
        ah.x += v0*x0.x + v1*x1.x + v2*x2.x + v3*x3.x;
        ah.y += v0*x0.y + v1*x1.y + v2*x2.y + v3*x3.y;
        ah.z += v0*x0.z + v1*x1.z + v2*x2.z + v3*x3.z;
        ah.w += v0*x0.w + v1*x1.w + v2*x2.w + v3*x3.w;
    }
    float part = o.x * (o.x - ah.x) + o.y * (o.y - ah.y) + o.z * (o.z - ah.z) + o.w * (o.w - ah.w);
    int w = threadIdx.x >> 5, lane = threadIdx.x & 31;
    float s = warp_sum(part);
    if (lane == 0) wred[w] = s;
    __syncthreads();
    if (threadIdx.x == 0) {
        float t = 0.0f;
        #pragma unroll
        for (int q = 0; q < 8; q++) t += wred[q];
        atomicAdd(dst, t);
    }
}

// ---------------- launch ----------------
extern "C" void kernel_launch(void* const* d_in, const int* in_sizes, int n_in,
                              void* d_out, int out_size) {
    const float* H   = (const float*)d_in[0];
    const float* A   = (const float*)d_in[1];
    const float* U   = (const float*)d_in[4];
    const float* lam = (const float*)d_in[5];
    const float* hw  = (const float*)d_in[6];
    const float* thr = (const float*)d_in[7];
    const float* gam = (const float*)d_in[8];
    const float* bet = (const float*)d_in[9];
    float* out  = (float*)d_out;
    float* tail = out + (size_t)Nn * Dd;   // [orth, lap_smooth, w0, w1, w2]

    k_setup<<<1, 32>>>(lam, hw, tail);
    k_csr_orth<<<518, 256>>>(A, U, tail + 0);

    k_spmm<<<Nn / 4, 256>>>(H, 0, 1);   // H1 = A @ H
    k_spmm<<<Nn / 4, 256>>>(H, 1, 2);   // H2 = A @ H1

    k_ZM<<<dim3(32, Kk), 256>>>(H, U);  // ZT + partial M, fused
    k_cholinv<<<Kk, 1024>>>();
    k_attn<<<dim3(Nn / 8, Kk), 256>>>();

    k_gemm<<<dim3(Nn / 64, Dd / 64), 256>>>(U);
    k_finalize<<<Nn / 4, 256>>>(H, thr, gam, bet, out);  // includes H3 gather
    k_lapsm<<<Nn / 4, 256>>>(out, tail + 1);
}

// round 11
// speedup vs baseline: 1.0306x; 1.0150x over previous
#include <cuda_runtime.h>
#include <math.h>

#define Nn 4096
#define Dd 256
#define Rr 32
#define Kk 3
#define MAXNZ 96
#define ETA 0.5f
#define COEFF 0.03125f          /* r/(n*eps^2) = 32/(4096*0.25) */
#define LN_EPS 1e-5f

// ---------------- device scratch ----------------
__device__ float g_H1[Nn*Dd];
__device__ float g_H2[Nn*Dd];
__device__ float g_ZT[Kk*Nn*Rr];       // [k][n][r]
__device__ float g_part[Kk*32*Rr*Rr];  // [k][chunk][32*32]
__device__ float g_Minv[Kk*Rr*Rr];
__device__ float g_Gcat[Nn*Kk*Rr];     // [n][k*32+r], pre-scaled by ETA*w_k
__device__ float g_agg[Nn*Dd];
__device__ int   g_nnz[Nn];            // true count
__device__ int   g_nnzp[Nn];           // padded to multiple of 8 (pad: col=row, val=0)
__device__ int   g_cols[Nn*MAXNZ];
__device__ float g_vals[Nn*MAXNZ];
__device__ float g_w[Kk];
__device__ float g_lap[Kk];

__device__ __forceinline__ float warp_sum(float v) {
    #pragma unroll
    for (int o = 16; o; o >>= 1) v += __shfl_xor_sync(0xFFFFFFFFu, v, o);
    return v;
}
__device__ __forceinline__ float warp_max(float v) {
    #pragma unroll
    for (int o = 16; o; o >>= 1) v = fmaxf(v, __shfl_xor_sync(0xFFFFFFFFu, v, o));
    return v;
}

// ---- merged: CSR (blocks 0..511) + orth (512..517) + setup (518) ----
__global__ void k_pre(const float* __restrict__ A, const float* __restrict__ U,
                      const float* __restrict__ lam, const float* __restrict__ hw,
                      float* __restrict__ tail) {
    if (blockIdx.x < 512) {
        int warp = threadIdx.x >> 5, lane = threadIdx.x & 31;
        int row = blockIdx.x * 8 + warp;
        const float4* ar = (const float4*)(A + (size_t)row * Nn);
        unsigned mlt = (1u << lane) - 1u;
        int base = 0;
        for (int c0 = 0; c0 < Nn / 4; c0 += 32) {
            float4 v = ar[c0 + lane];
            unsigned b0 = __ballot_sync(0xFFFFFFFFu, v.x != 0.0f);
            unsigned b1 = __ballot_sync(0xFFFFFFFFu, v.y != 0.0f);
            unsigned b2 = __ballot_sync(0xFFFFFFFFu, v.z != 0.0f);
            unsigned b3 = __ballot_sync(0xFFFFFFFFu, v.w != 0.0f);
            int pos = base + __popc(b0 & mlt) + __popc(b1 & mlt)
                           + __popc(b2 & mlt) + __popc(b3 & mlt);
            int cbase = (c0 + lane) * 4;
            if (v.x != 0.0f && pos < MAXNZ) { g_cols[row*MAXNZ+pos] = cbase;     g_vals[row*MAXNZ+pos] = v.x; pos++; }
            if (v.y != 0.0f && pos < MAXNZ) { g_cols[row*MAXNZ+pos] = cbase + 1; g_vals[row*MAXNZ+pos] = v.y; pos++; }
            if (v.z != 0.0f && pos < MAXNZ) { g_cols[row*MAXNZ+pos] = cbase + 2; g_vals[row*MAXNZ+pos] = v.z; pos++; }
            if (v.w != 0.0f && pos < MAXNZ) { g_cols[row*MAXNZ+pos] = cbase + 3; g_vals[row*MAXNZ+pos] = v.w; pos++; }
            base += __popc(b0) + __popc(b1) + __popc(b2) + __popc(b3);
        }
        if (base > MAXNZ) base = MAXNZ;
        int padded = (base + 7) & ~7;
        if (padded > MAXNZ) padded = MAXNZ;
        for (int i = base + lane; i < padded; i += 32) {
            g_cols[row * MAXNZ + i] = row;
            g_vals[row * MAXNZ + i] = 0.0f;
        }
        if (lane == 0) { g_nnz[row] = base; g_nnzp[row] = padded; }
    } else if (blockIdx.x < 518) {
        const int pk[6] = {0,0,0,1,1,2}, pl[6] = {0,1,2,1,2,2};
        int p = blockIdx.x - 512;
        int k = pk[p], l = pl[p];
        int ab = threadIdx.x >> 5, b = threadIdx.x & 31;
        const float* Ua = U + k * Dd * Rr;
        const float* Ub = U + l * Dd * Rr;
        float tot = 0.0f;
        for (int ao = 0; ao < 4; ao++) {
            int a = ao * 8 + ab;
            float g = 0.0f;
            #pragma unroll 8
            for (int d = 0; d < Dd; d++) g += Ua[d * Rr + a] * Ub[d * Rr + b];
            if (k == l && a == b) g -= 1.0f;
            tot += g * g;
        }
        __shared__ float wred[8];
        int w = threadIdx.x >> 5, lane = threadIdx.x & 31;
        float s = warp_sum(tot);
        if (lane == 0) wred[w] = s;
        __syncthreads();
        if (threadIdx.x == 0) {
            float t = 0.0f;
            #pragma unroll
            for (int q = 0; q < 8; q++) t += wred[q];
            atomicAdd(tail + 0, t);
        }
    } else {
        if (threadIdx.x == 0) {
            float h0 = hw[0], h1 = hw[1], h2 = hw[2];
            float mx = fmaxf(h0, fmaxf(h1, h2));
            float e0 = expf(h0 - mx), e1 = expf(h1 - mx), e2 = expf(h2 - mx);
            float inv = 1.0f / (e0 + e1 + e2);
            g_w[0] = e0 * inv; g_w[1] = e1 * inv; g_w[2] = e2 * inv;
            for (int k = 0; k < Kk; k++) g_lap[k] = log1pf(expf(lam[k]));
            tail[1] = 0.0f;
            tail[2] = g_w[0]; tail[3] = g_w[1]; tail[4] = g_w[2];
        }
    }
}

// ---------------- SpMM float4, 4 rows per block, branch-free unroll-8 ----------------
__global__ void k_spmm(const float* __restrict__ H0, int src_id, int dst_id) {
    int rl = threadIdx.x >> 6, d4 = threadIdx.x & 63;
    int m = blockIdx.x * 4 + rl;
    __shared__ int   csh[4][MAXNZ];
    __shared__ float vsh[4][MAXNZ];
    int nzp = g_nnzp[m];
    for (int i = d4; i < nzp; i += 64) {
        csh[rl][i] = g_cols[m * MAXNZ + i];
        vsh[rl][i] = g_vals[m * MAXNZ + i];
    }
    __syncthreads();
    const float4* src = (const float4*)((src_id == 0) ? H0 : g_H1);
    float4 acc = make_float4(0.f, 0.f, 0.f, 0.f);
    for (int i = 0; i < nzp; i += 8) {
        float4 x0 = src[csh[rl][i    ] * 64 + d4];
        float4 x1 = src[csh[rl][i + 1] * 64 + d4];
        float4 x2 = src[csh[rl][i + 2] * 64 + d4];
        float4 x3 = src[csh[rl][i + 3] * 64 + d4];
        float4 x4 = src[csh[rl][i + 4] * 64 + d4];
        float4 x5 = src[csh[rl][i + 5] * 64 + d4];
        float4 x6 = src[csh[rl][i + 6] * 64 + d4];
        float4 x7 = src[csh[rl][i + 7] * 64 + d4];
        float v0 = vsh[rl][i],     v1 = vsh[rl][i + 1], v2 = vsh[rl][i + 2], v3 = vsh[rl][i + 3];
        float v4 = vsh[rl][i + 4], v5 = vsh[rl][i + 5], v6 = vsh[rl][i + 6], v7 = vsh[rl][i + 7];
        acc.x += v0*x0.x + v1*x1.x + v2*x2.x + v3*x3.x + v4*x4.x + v5*x5.x + v6*x6.x + v7*x7.x;
        acc.y += v0*x0.y + v1*x1.y + v2*x2.y + v3*x3.y + v4*x4.y + v5*x5.y + v6*x6.y + v7*x7.y;
        acc.z += v0*x0.z + v1*x1.z + v2*x2.z + v3*x3.z + v4*x4.z + v5*x5.z + v6*x6.z + v7*x7.z;
        acc.w += v0*x0.w + v1*x1.w + v2*x2.w + v3*x3.w + v4*x4.w + v5*x5.w + v6*x6.w + v7*x7.w;
    }
    float4* dst = (float4*)((dst_id == 1) ? g_H1 : g_H2);
    dst[m * 64 + d4] = acc;
}

// ---------------- fused: ZT tile GEMM + partial M (grid 32 x 3) ----------------
__global__ void k_ZM(const float* __restrict__ H0, const float* __restrict__ U) {
    __shared__ float Hs[128 * 33];
    __shared__ float Us[32][32];
    int kz = blockIdx.y;
    const float* src = (kz == 0) ? H0 : (kz == 1) ? g_H1 : g_H2;
    const float* Uk = U + kz * Dd * Rr;
    int n0 = blockIdx.x * 128;
    int tx = threadIdx.x & 15;
    int ty = threadIdx.x >> 4;
    float acc[8][2];
    #pragma unroll
    for (int q = 0; q < 8; q++) { acc[q][0] = 0.f; acc[q][1] = 0.f; }
    for (int d0 = 0; d0 < Dd; d0 += 32) {
        const float4* s4 = (const float4*)(src + (size_t)n0 * Dd + d0);
        int rr = threadIdx.x >> 3, cc = threadIdx.x & 7;
        #pragma unroll
        for (int q = 0; q < 4; q++) {
            float4 v = s4[(rr + q * 32) * 64 + cc];
            float* hp = &Hs[(rr + q * 32) * 33 + cc * 4];
            hp[0] = v.x; hp[1] = v.y; hp[2] = v.z; hp[3] = v.w;
        }
        int kk = threadIdx.x >> 3, c4 = threadIdx.x & 7;
        *(float4*)&Us[kk][c4 * 4] = *(const float4*)&Uk[(d0 + kk) * Rr + c4 * 4];
        __syncthreads();
        #pragma unroll
        for (int k2 = 0; k2 < 32; k2++) {
            float b0 = Us[k2][tx * 2], b1 = Us[k2][tx * 2 + 1];
            #pragma unroll
            for (int q = 0; q < 8; q++) {
                float a = Hs[(ty * 8 + q) * 33 + k2];
                acc[q][0] += a * b0; acc[q][1] += a * b1;
            }
        }
        __syncthreads();
    }
    #pragma unroll
    for (int q = 0; q < 8; q++) {
        int n = ty * 8 + q;
        *(float2*)&g_ZT[kz * Nn * Rr + (n0 + n) * Rr + tx * 2] = make_float2(acc[q][0], acc[q][1]);
        Hs[n * 33 + tx * 2] = acc[q][0];
        Hs[n * 33 + tx * 2 + 1] = acc[q][1];
    }
    __syncthreads();
    int i0 = (threadIdx.x >> 4) * 2, j0 = (threadIdx.x & 15) * 2;
    float a00 = 0.f, a01 = 0.f, a10 = 0.f, a11 = 0.f;
    #pragma unroll 4
    for (int n = 0; n < 128; n++) {
        float zi0 = Hs[n * 33 + i0], zi1 = Hs[n * 33 + i0 + 1];
        float zj0 = Hs[n * 33 + j0], zj1 = Hs[n * 33 + j0 + 1];
        a00 += zi0 * zj0; a01 += zi0 * zj1;
        a10 += zi1 * zj0; a11 += zi1 * zj1;
    }
    float* p = g_part + (kz * 32 + blockIdx.x) * Rr * Rr;
    p[i0 * 32 + j0] = a00; p[i0 * 32 + j0 + 1] = a01;
    p[(i0 + 1) * 32 + j0] = a10; p[(i0 + 1) * 32 + j0 + 1] = a11;
}

// ---------------- reduce + Cholesky + inverse (3 blocks of 1024) ----------------
__global__ void k_cholinv() {
    __shared__ float Msh[Rr * 33];
    __shared__ float ysh[Rr * 33];
    int kz = blockIdx.x;
    int tid = threadIdx.x;
    int i = tid >> 5, j = tid & 31;
    float s = 0.0f;
    #pragma unroll
    for (int b = 0; b < 32; b++) s += g_part[(kz * 32 + b) * Rr * Rr + tid];
    Msh[i * 33 + j] = COEFF * s + (i == j ? 1.0f : 0.0f);
    __syncthreads();
    for (int k2 = 0; k2 < Rr; k2++) {
        if (tid == 0) Msh[k2 * 33 + k2] = sqrtf(Msh[k2 * 33 + k2]);
        __syncthreads();
        if (j == k2 && i > k2) Msh[i * 33 + k2] /= Msh[k2 * 33 + k2];
        __syncthreads();
        if (i > k2 && j > k2 && j <= i) Msh[i * 33 + j] -= Msh[i * 33 + k2] * Msh[j * 33 + k2];
        __syncthreads();
    }
    int c = i, lane = j;
    for (int r = 0; r < Rr; r++) {
        float contrib = (lane < r) ? Msh[r * 33 + lane] * ysh[c * 33 + lane] : 0.0f;
        contrib = warp_sum(contrib);
        if (lane == 0) ysh[c * 33 + r] = (((r == c) ? 1.0f : 0.0f) - contrib) / Msh[r * 33 + r];
        __syncwarp();
    }
    for (int r = Rr - 1; r >= 0; r--) {
        float contrib = (lane > r) ? Msh[lane * 33 + r] * ysh[c * 33 + lane] : 0.0f;
        contrib = warp_sum(contrib);
        if (lane == 0) ysh[c * 33 + r] = (ysh[c * 33 + r] - contrib) / Msh[r * 33 + r];
        __syncwarp();
    }
    __syncthreads();
    g_Minv[kz * Rr * Rr + i * 32 + j] = ysh[j * 33 + i];
}

// ---------------- attention (round-5 version: small smem, warp per row) ----------------
__global__ void k_attn() {
    __shared__ float Mi[Rr * 33];
    __shared__ float ssh[8][MAXNZ];
    int kz = blockIdx.y;
    int tid = threadIdx.x;
    for (int q = tid; q < Rr * Rr; q += 256)
        Mi[(q >> 5) * 33 + (q & 31)] = g_Minv[kz * Rr * Rr + q];
    __syncthreads();
    int w = tid >> 5, lane = tid & 31;
    int m = blockIdx.x * 8 + w;
    int nz = g_nnz[m];
    const int* cp = &g_cols[m * MAXNZ];
    const float* ZTk = g_ZT + kz * Nn * Rr;
    float z = ZTk[m * Rr + lane];
    // qp[s] = sum_r z[r] * Minv[r][s]
    float qp = 0.0f;
    #pragma unroll
    for (int r = 0; r < Rr; r++)
        qp += Mi[r * 33 + lane] * __shfl_sync(0xFFFFFFFFu, z, r);
    // scores over neighbors
    for (int i0 = 0; i0 < nz; i0 += 4) {
        int c0 = cp[i0];
        int c1 = (i0 + 1 < nz) ? cp[i0 + 1] : c0;
        int c2 = (i0 + 2 < nz) ? cp[i0 + 2] : c0;
        int c3 = (i0 + 3 < nz) ? cp[i0 + 3] : c0;
        float p0 = warp_sum(qp * ZTk[c0 * Rr + lane]);
        float p1 = warp_sum(qp * ZTk[c1 * Rr + lane]);
        float p2 = warp_sum(qp * ZTk[c2 * Rr + lane]);
        float p3 = warp_sum(qp * ZTk[c3 * Rr + lane]);
        if (lane == 0) {
            ssh[w][i0] = p0;
            if (i0 + 1 < nz) ssh[w][i0 + 1] = p1;
            if (i0 + 2 < nz) ssh[w][i0 + 2] = p2;
            if (i0 + 3 < nz) ssh[w][i0 + 3] = p3;
        }
    }
    __syncwarp();
    float mx = -1e30f;
    for (int i = lane; i < nz; i += 32) mx = fmaxf(mx, ssh[w][i]);
    mx = warp_max(mx);
    float sm = 0.0f;
    for (int i = lane; i < nz; i += 32) {
        float e = expf(ssh[w][i] - mx);
        ssh[w][i] = e; sm += e;
    }
    sm = warp_sum(sm);
    float inv = 1.0f / sm;
    __syncwarp();
    // t = sum_j alpha_j * z_j
    float t = 0.0f;
    int i = 0;
    for (; i + 4 <= nz; i += 4) {
        float m0 = ZTk[cp[i]     * Rr + lane];
        float m1 = ZTk[cp[i + 1] * Rr + lane];
        float m2 = ZTk[cp[i + 2] * Rr + lane];
        float m3 = ZTk[cp[i + 3] * Rr + lane];
        t += ssh[w][i] * m0 + ssh[w][i + 1] * m1 + ssh[w][i + 2] * m2 + ssh[w][i + 3] * m3;
    }
    for (; i < nz; i++) t += ssh[w][i] * ZTk[cp[i] * Rr + lane];
    t *= inv;
    // out[r] = sum_s Minv[r][s] * t[s]
    float o = 0.0f;
    #pragma unroll
    for (int s2 = 0; s2 < Rr; s2++)
        o += Mi[lane * 33 + s2] * __shfl_sync(0xFFFFFFFFu, t, s2);
    g_Gcat[m * (Kk * Rr) + kz * Rr + lane] = o * (ETA * g_w[kz]);
}

// ---------------- agg = Gcat @ Ucat: tiled 64x64, 4x4 per thread ----------------
__global__ void k_gemm(const float* __restrict__ U) {
    __shared__ float Gs[64][33];
    __shared__ float Us[32][65];
    int n0 = blockIdx.x * 64, d0 = blockIdx.y * 64;
    int tx = threadIdx.x & 15, ty = threadIdx.x >> 4;
    float acc[4][4];
    #pragma unroll
    for (int a = 0; a < 4; a++)
        #pragma unroll
        for (int b = 0; b < 4; b++) acc[a][b] = 0.f;
    for (int k = 0; k < Kk; k++) {
        __syncthreads();
        #pragma unroll
        for (int q = 0; q < 8; q++) {
            int idx = threadIdx.x + 256 * q;
            int gi = idx >> 5, gr = idx & 31;
            Gs[gi][gr] = g_Gcat[(n0 + gi) * (Kk * Rr) + k * Rr + gr];
            Us[gr][gi] = U[k * Dd * Rr + (d0 + gi) * Rr + gr];
        }
        __syncthreads();
        #pragma unroll
        for (int r = 0; r < Rr; r++) {
            float a[4], b[4];
            #pragma unroll
            for (int q = 0; q < 4; q++) a[q] = Gs[ty * 4 + q][r];
            #pragma unroll
            for (int p = 0; p < 4; p++) b[p] = Us[r][tx * 4 + p];
            #pragma unroll
            for (int q = 0; q < 4; q++)
                #pragma unroll
                for (int p = 0; p < 4; p++) acc[q][p] += a[q] * b[p];
        }
    }
    #pragma unroll
    for (int q = 0; q < 4; q++) {
        float4 v = make_float4(acc[q][0], acc[q][1], acc[q][2], acc[q][3]);
        *(float4*)&g_agg[(size_t)(n0 + ty * 4 + q) * Dd + d0 + tx * 4] = v;
    }
}

// ---------------- finalize: inline H3 gather + threshold + residual + LN; 4 rows/block ----------------
__global__ void k_finalize(const float* __restrict__ H0, const float* __restrict__ thr,
                           const float* __restrict__ gam, const float* __restrict__ bet,
                           float* __restrict__ out) {
    int rl = threadIdx.x >> 6, t64 = threadIdx.x & 63;
    int m = blockIdx.x * 4 + rl;
    __shared__ int   csh[4][MAXNZ];
    __shared__ float vsh[4][MAXNZ];
    __shared__ float wred[8][2];
    int nzp = g_nnzp[m];
    for (int i = t64; i < nzp; i += 64) {
        csh[rl][i] = g_cols[m * MAXNZ + i];
        vsh[rl][i] = g_vals[m * MAXNZ + i];
    }
    __syncthreads();
    const float4* H0_4 = (const float4*)H0;
    const float4* H1_4 = (const float4*)g_H1;
    const float4* H2_4 = (const float4*)g_H2;
    const float4* ag4  = (const float4*)g_agg;
    int idx4 = m * 64 + t64;
    float4 x  = H0_4[idx4];
    float4 h1 = H1_4[idx4];
    float4 h2 = H2_4[idx4];
    float4 ag = ag4[idx4];
    float4 h3 = make_float4(0.f, 0.f, 0.f, 0.f);
    for (int i = 0; i < nzp; i += 4) {
        float4 x0 = H2_4[csh[rl][i]     * 64 + t64];
        float4 x1 = H2_4[csh[rl][i + 1] * 64 + t64];
        float4 x2 = H2_4[csh[rl][i + 2] * 64 + t64];
        float4 x3 = H2_4[csh[rl][i + 3] * 64 + t64];
        float v0 = vsh[rl][i], v1 = vsh[rl][i + 1], v2 = vsh[rl][i + 2], v3 = vsh[rl][i + 3];
        h3.x += v0*x0.x + v1*x1.x + v2*x2.x + v3*x3.x;
        h3.y += v0*x0.y + v1*x1.y + v2*x2.y + v3*x3.y;
        h3.z += v0*x0.z + v1*x1.z + v2*x2.z + v3*x3.z;
        h3.w += v0*x0.w + v1*x1.w + v2*x2.w + v3*x3.w;
    }
    float l0 = g_lap[0], l1 = g_lap[1], l2 = g_lap[2];
    float4 t4 = ((const float4*)thr)[t64];
    float y[4];
    {
        float xs[4] = {x.x, x.y, x.z, x.w};
        float a1[4] = {h1.x, h1.y, h1.z, h1.w};
        float a2[4] = {h2.x, h2.y, h2.z, h2.w};
        float a3[4] = {h3.x, h3.y, h3.z, h3.w};
        float ags[4] = {ag.x, ag.y, ag.z, ag.w};
        float ts[4] = {t4.x, t4.y, t4.z, t4.w};
        #pragma unroll
        for (int q = 0; q < 4; q++) {
            float lap = l0 * (xs[q] - a1[q]) + l1 * (a1[q] - a2[q]) + l2 * (a2[q] - a3[q]);
            float h = xs[q] + ags[q] - ETA * lap;
            float a = fabsf(h) - ts[q];
            float yv = (a > 0.0f) ? copysignf(a, h) : 0.0f;
            y[q] = yv + xs[q];
        }
    }
    float s1 = y[0] + y[1] + y[2] + y[3];
    float s2 = y[0]*y[0] + y[1]*y[1] + y[2]*y[2] + y[3]*y[3];
    s1 = warp_sum(s1); s2 = warp_sum(s2);
    int w = threadIdx.x >> 5, lane = threadIdx.x & 31;
    if (lane == 0) { wred[w][0] = s1; wred[w][1] = s2; }
    __syncthreads();
    float mu  = (wred[rl*2][0] + wred[rl*2+1][0]) * (1.0f / Dd);
    float ex2 = (wred[rl*2][1] + wred[rl*2+1][1]) * (1.0f / Dd);
    float inv_sd = rsqrtf(ex2 - mu * mu + LN_EPS);
    float4 g4 = ((const float4*)gam)[t64];
    float4 b4 = ((const float4*)bet)[t64];
    float4 o4;
    o4.x = (y[0] - mu) * inv_sd * g4.x + b4.x;
    o4.y = (y[1] - mu) * inv_sd * g4.y + b4.y;
    o4.z = (y[2] - mu) * inv_sd * g4.z + b4.z;
    o4.w = (y[3] - mu) * inv_sd * g4.w + b4.w;
    ((float4*)out)[idx4] = o4;
}

// ---------------- lap_smooth = sum(H_out * (H_out - A@H_out)); 4 rows/block ----------------
__global__ void k_lapsm(const float* __restrict__ out, float* __restrict__ dst) {
    int rl = threadIdx.x >> 6, t64 = threadIdx.x & 63;
    int m = blockIdx.x * 4 + rl;
    __shared__ int   csh[4][MAXNZ];
    __shared__ float vsh[4][MAXNZ];
    __shared__ float wred[8];
    int nzp = g_nnzp[m];
    for (int i = t64; i < nzp; i += 64) {
        csh[rl][i] = g_cols[m * MAXNZ + i];
        vsh[rl][i] = g_vals[m * MAXNZ + i];
    }
    __syncthreads();
    const float4* o4 = (const float4*)out;
    float4 o = o4[m * 64 + t64];
    float4 ah = make_float4(0.f, 0.f, 0.f, 0.f);
    for (int i = 0; i < nzp; i += 4) {
        float4 x0 = o4[csh[rl][i]     * 64 + t64];
        float4 x1 = o4[csh[rl][i + 1] * 64 + t64];
        float4 x2 = o4[csh[rl][i + 2] * 64 + t64];
        float4 x3 = o4[csh[rl][i + 3] * 64 + t64];
        float v0 = vsh[rl][i], v1 = vsh[rl][i + 1], v2 = vsh[rl][i + 2], v3 = vsh[rl][i + 3];
        ah.x += v0*x0.x + v1*x1.x + v2*x2.x + v3*x3.x;
        ah.y += v0*x0.y + v1*x1.y + v2*x2.y + v3*x3.y;
        ah.z += v0*x0.z + v1*x1.z + v2*x2.z + v3*x3.z;
        ah.w += v0*x0.w + v1*x1.w + v2*x2.w + v3*x3.w;
    }
    float part = o.x * (o.x - ah.x) + o.y * (o.y - ah.y) + o.z * (o.z - ah.z) + o.w * (o.w - ah.w);
    int w = threadIdx.x >> 5, lane = threadIdx.x & 31;
    float s = warp_sum(part);
    if (lane == 0) wred[w] = s;
    __syncthreads();
    if (threadIdx.x == 0) {
        float t = 0.0f;
        #pragma unroll
        for (int q = 0; q < 8; q++) t += wred[q];
        atomicAdd(dst, t);
    }
}

// ---------------- launch ----------------
extern "C" void kernel_launch(void* const* d_in, const int* in_sizes, int n_in,
                              void* d_out, int out_size) {
    const float* H   = (const float*)d_in[0];
    const float* A   = (const float*)d_in[1];
    const float* U   = (const float*)d_in[4];
    const float* lam = (const float*)d_in[5];
    const float* hw  = (const float*)d_in[6];
    const float* thr = (const float*)d_in[7];
    const float* gam = (const float*)d_in[8];
    const float* bet = (const float*)d_in[9];
    float* out  = (float*)d_out;
    float* tail = out + (size_t)Nn * Dd;   // [orth, lap_smooth, w0, w1, w2]

    // NOTE: tail[0] (orth) is accumulated atomically by blocks 512..517; it must
    // start at 0. d_out is poisoned, so zero it from the same kernel? No — CSR
    // blocks and orth blocks run concurrently with block 518's tail writes.
    // Solution: orth blocks atomically add to tail[0] AFTER it is zeroed by a
    // tiny preceding kernel. Keep a separate zeroing launch for safety.
    // (cudaMemsetAsync on d_out region is graph-capturable.)
    cudaMemsetAsync(tail, 0, 2 * sizeof(float));
    k_pre<<<519, 256>>>(A, U, lam, hw, tail);

    k_spmm<<<Nn / 4, 256>>>(H, 0, 1);   // H1 = A @ H
    k_spmm<<<Nn / 4, 256>>>(H, 1, 2);   // H2 = A @ H1

    k_ZM<<<dim3(32, Kk), 256>>>(H, U);  // ZT + partial M, fused
    k_cholinv<<<Kk, 1024>>>();
    k_attn<<<dim3(Nn / 8, Kk), 256>>>();

    k_gemm<<<dim3(Nn / 64, Dd / 64), 256>>>(U);
    k_finalize<<<Nn / 4, 256>>>(H, thr, gam, bet, out);  // includes H3 gather
    k_lapsm<<<Nn / 4, 256>>>(out, tail + 1);
}